// round 6
// baseline (speedup 1.0000x reference)
#include <cuda_runtime.h>
#include <math.h>

#define BATCH   4
#define SEQ     2048
#define DMODEL  1024
#define NHEADS  16
#define DHEAD   64
#define BS      (BATCH * SEQ)          // 8192
#define HD      (SEQ * DHEAD)          // per (b,h) plane: 131072

// Scratch (allocation-free rule: __device__ globals). 32 MB each.
__device__ float g_Q[BATCH * NHEADS * SEQ * DHEAD];
__device__ float g_K[BATCH * NHEADS * SEQ * DHEAD];
__device__ float g_V[BATCH * NHEADS * SEQ * DHEAD];
__device__ float g_O[BATCH * NHEADS * SEQ * DHEAD];

// ---------------------------------------------------------------------------
// Kernel 1: fused QKV projection.
// C[8192, 3072] = X[8192,1024] * [Wq|Wk|Wv], written directly into g_Q/g_K/g_V
// with [b,h,s,d] layout. 128x128x16 tile, 256 threads, 8x8 per thread.
// ---------------------------------------------------------------------------
__global__ __launch_bounds__(256) void qkv_kernel(
    const float* __restrict__ X,
    const float* __restrict__ Wq,
    const float* __restrict__ Wk,
    const float* __restrict__ Wv)
{
    __shared__ float Xs[16][132];
    __shared__ float Ws[16][132];

    const int t  = threadIdx.x;
    const int tx = t & 15;          // 0..15  -> 8 output cols
    const int ty = t >> 4;          // 0..15  -> 8 output rows
    const int rowBase = blockIdx.y * 128;   // 0..8064
    const int colBase = blockIdx.x * 128;   // 0..2944 (over 3*1024)
    const int which   = colBase >> 10;      // 0=Q 1=K 2=V (128 | 1024)
    const int cB      = colBase & 1023;

    const float* __restrict__ W = (which == 0) ? Wq : (which == 1) ? Wk : Wv;
    float* __restrict__ dstBuf   = (which == 0) ? g_Q : (which == 1) ? g_K : g_V;

    float acc[8][8] = {};

    for (int k0 = 0; k0 < DMODEL; k0 += 16) {
        // Load X tile transposed: Xs[k][row]
        #pragma unroll
        for (int i = 0; i < 8; i++) {
            int idx = t + i * 256;
            int kk = idx & 15, r = idx >> 4;
            Xs[kk][r] = X[(rowBase + r) * DMODEL + k0 + kk];
        }
        // Load W tile: Ws[k][c], W is [h, m, d] so (m, col=h*64+d) -> h*65536 + m*64 + d
        #pragma unroll
        for (int i = 0; i < 8; i++) {
            int idx = t + i * 256;
            int c = idx & 127, kk = idx >> 7;
            int col = cB + c;
            int h = col >> 6, d = col & 63;
            Ws[kk][c] = W[h * (DMODEL * DHEAD) + (k0 + kk) * DHEAD + d];
        }
        __syncthreads();

        #pragma unroll
        for (int kk = 0; kk < 16; kk++) {
            float a[8], b[8];
            *(float4*)&a[0] = *(const float4*)&Xs[kk][ty * 8];
            *(float4*)&a[4] = *(const float4*)&Xs[kk][ty * 8 + 4];
            *(float4*)&b[0] = *(const float4*)&Ws[kk][tx * 8];
            *(float4*)&b[4] = *(const float4*)&Ws[kk][tx * 8 + 4];
            #pragma unroll
            for (int i = 0; i < 8; i++)
                #pragma unroll
                for (int j = 0; j < 8; j++)
                    acc[i][j] = fmaf(a[i], b[j], acc[i][j]);
        }
        __syncthreads();
    }

    // Write into [b,h,s,d]
    #pragma unroll
    for (int i = 0; i < 8; i++) {
        int r  = rowBase + ty * 8 + i;
        int bb = r >> 11;           // / SEQ
        int s  = r & 2047;
        #pragma unroll
        for (int j = 0; j < 8; j++) {
            int col = cB + tx * 8 + j;
            int h = col >> 6, d = col & 63;
            dstBuf[((bb * NHEADS + h) * SEQ + s) * DHEAD + d] = acc[i][j];
        }
    }
}

// ---------------------------------------------------------------------------
// Kernel 2: causal flash attention, one (b,h) per blockIdx.y, 128 q-rows per
// query tile, 64-key tiles. 256 threads: ty=t/8 (4 rows each), tx=t%8
// (interleaved cols c = tx + 8*j -> conflict-free shared reads).
// Query tiles mapped longest-first (qt = 15 - blockIdx.x) to kill the
// causal-imbalance straggler tail.
// ---------------------------------------------------------------------------
#define STR 65
#define ATTN_SMEM ((128 * STR + 64 * STR + 64 * STR + 128 * STR) * 4)  // 99840 B

__global__ __launch_bounds__(256) void attn_kernel()
{
    extern __shared__ float sm[];
    float* Qs = sm;                        // [128][STR]
    float* Ks = Qs + 128 * STR;            // [64][STR]
    float* Vs = Ks + 64 * STR;             // [64][STR]
    float* Ps = Vs + 64 * STR;             // [128][STR]

    const int t  = threadIdx.x;
    const int tx = t & 7;                  // col group (interleaved)
    const int ty = t >> 3;                 // 0..31, rows ty*4..ty*4+3
    const int qt = (gridDim.x - 1) - blockIdx.x;   // longest blocks first
    const int bh = blockIdx.y;             // b*16 + h

    const float* __restrict__ Qp = g_Q + bh * HD;
    const float* __restrict__ Kp = g_K + bh * HD;
    const float* __restrict__ Vp = g_V + bh * HD;

    // Load Q tile (128x64) with float4 global loads (scalar STS: 65-pad
    // breaks 16B shared alignment).
    #pragma unroll
    for (int i = 0; i < 8; i++) {
        int idx = t + i * 256;             // 2048 float4s
        int r = idx >> 4, d4 = (idx & 15) * 4;
        float4 v = *(const float4*)&Qp[(qt * 128 + r) * DHEAD + d4];
        Qs[r * STR + d4 + 0] = v.x;
        Qs[r * STR + d4 + 1] = v.y;
        Qs[r * STR + d4 + 2] = v.z;
        Qs[r * STR + d4 + 3] = v.w;
    }

    float mrow[4], lrow[4], Oacc[4][8];
    #pragma unroll
    for (int i = 0; i < 4; i++) {
        mrow[i] = -INFINITY;
        lrow[i] = 0.0f;
        #pragma unroll
        for (int j = 0; j < 8; j++) Oacc[i][j] = 0.0f;
    }

    const int nkt = 2 * qt + 2;            // causal tile bound
    const int qr0 = qt * 128 + ty * 4;

    for (int jt = 0; jt < nkt; jt++) {
        // Load K,V tiles (64x64) with float4 global loads
        #pragma unroll
        for (int i = 0; i < 4; i++) {
            int idx = t + i * 256;         // 1024 float4s
            int c = idx >> 4, d4 = (idx & 15) * 4;
            float4 kv = *(const float4*)&Kp[(jt * 64 + c) * DHEAD + d4];
            float4 vv = *(const float4*)&Vp[(jt * 64 + c) * DHEAD + d4];
            Ks[c * STR + d4 + 0] = kv.x;  Ks[c * STR + d4 + 1] = kv.y;
            Ks[c * STR + d4 + 2] = kv.z;  Ks[c * STR + d4 + 3] = kv.w;
            Vs[c * STR + d4 + 0] = vv.x;  Vs[c * STR + d4 + 1] = vv.y;
            Vs[c * STR + d4 + 2] = vv.z;  Vs[c * STR + d4 + 3] = vv.w;
        }
        __syncthreads();

        // S = Q K^T  (rows ty*4+i, cols tx+8*j)
        float sc[4][8] = {};
        #pragma unroll 8
        for (int d = 0; d < 64; d++) {
            float a[4], b[8];
            #pragma unroll
            for (int i = 0; i < 4; i++) a[i] = Qs[(ty * 4 + i) * STR + d];
            #pragma unroll
            for (int j = 0; j < 8; j++) b[j] = Ks[(tx + 8 * j) * STR + d];
            #pragma unroll
            for (int i = 0; i < 4; i++)
                #pragma unroll
                for (int j = 0; j < 8; j++)
                    sc[i][j] = fmaf(a[i], b[j], sc[i][j]);
        }

        // scale + causal mask + online softmax
        #pragma unroll
        for (int i = 0; i < 4; i++) {
            const int qr = qr0 + i;
            float pm = -INFINITY;
            #pragma unroll
            for (int j = 0; j < 8; j++) {
                int kc = jt * 64 + tx + 8 * j;
                float v = sc[i][j] * 0.125f;           // 1/sqrt(64)
                v = (kc <= qr) ? v : -INFINITY;
                sc[i][j] = v;
                pm = fmaxf(pm, v);
            }
            // reduce max over the 8-lane col group
            pm = fmaxf(pm, __shfl_xor_sync(0xffffffffu, pm, 1));
            pm = fmaxf(pm, __shfl_xor_sync(0xffffffffu, pm, 2));
            pm = fmaxf(pm, __shfl_xor_sync(0xffffffffu, pm, 4));

            float newm = fmaxf(mrow[i], pm);
            float corr = __expf(mrow[i] - newm);       // 0 on first tile
            mrow[i] = newm;

            float psum = 0.0f;
            #pragma unroll
            for (int j = 0; j < 8; j++) {
                float p = __expf(sc[i][j] - newm);     // masked -> 0
                sc[i][j] = p;
                psum += p;
            }
            psum += __shfl_xor_sync(0xffffffffu, psum, 1);
            psum += __shfl_xor_sync(0xffffffffu, psum, 2);
            psum += __shfl_xor_sync(0xffffffffu, psum, 4);

            lrow[i] = lrow[i] * corr + psum;
            #pragma unroll
            for (int j = 0; j < 8; j++) Oacc[i][j] *= corr;
        }

        // Stage P to shared
        #pragma unroll
        for (int i = 0; i < 4; i++)
            #pragma unroll
            for (int j = 0; j < 8; j++)
                Ps[(ty * 4 + i) * STR + (tx + 8 * j)] = sc[i][j];
        __syncthreads();

        // O += P * V   (d cols = tx + 8*j, interleaved: conflict-free)
        #pragma unroll 8
        for (int c = 0; c < 64; c++) {
            float p[4], vv[8];
            #pragma unroll
            for (int i = 0; i < 4; i++) p[i] = Ps[(ty * 4 + i) * STR + c];
            #pragma unroll
            for (int j = 0; j < 8; j++) vv[j] = Vs[c * STR + tx + 8 * j];
            #pragma unroll
            for (int i = 0; i < 4; i++)
                #pragma unroll
                for (int j = 0; j < 8; j++)
                    Oacc[i][j] = fmaf(p[i], vv[j], Oacc[i][j]);
        }
        __syncthreads();   // protect Ks/Vs/Ps before next tile
    }

    // Normalize and write out [b,h,s,d]
    float* __restrict__ Op = g_O + bh * HD;
    #pragma unroll
    for (int i = 0; i < 4; i++) {
        float inv = 1.0f / lrow[i];
        int qr = qr0 + i;
        #pragma unroll
        for (int j = 0; j < 8; j++)
            Op[qr * DHEAD + (tx + 8 * j)] = Oacc[i][j] * inv;
    }
}

// ---------------------------------------------------------------------------
// Kernel 3: output projection. out[8192,1024] = concat(O)[8192,1024] * Wout.
// Head-concat permutation (m = h*64+d -> g_O[b,h,s,d]) folded into the A-tile
// load. 128x128x16 tiles, 256 threads, 8x8 per thread.
// ---------------------------------------------------------------------------
__global__ __launch_bounds__(256) void outproj_kernel(
    const float* __restrict__ Wout,
    float* __restrict__ out)
{
    __shared__ float As[16][132];
    __shared__ float Ws[16][132];

    const int t  = threadIdx.x;
    const int tx = t & 15;
    const int ty = t >> 4;
    const int rowBase = blockIdx.y * 128;
    const int colBase = blockIdx.x * 128;

    float acc[8][8] = {};

    for (int k0 = 0; k0 < DMODEL; k0 += 16) {
        const int h = k0 >> 6;             // 16 | 64: whole tile in one head
        #pragma unroll
        for (int i = 0; i < 8; i++) {
            int idx = t + i * 256;
            int kk = idx & 15, r = idx >> 4;
            int d  = (k0 + kk) & 63;
            int rr = rowBase + r;
            int bb = rr >> 11, s = rr & 2047;
            As[kk][r] = g_O[((bb * NHEADS + h) * SEQ + s) * DHEAD + d];
        }
        #pragma unroll
        for (int i = 0; i < 8; i++) {
            int idx = t + i * 256;
            int c = idx & 127, kk = idx >> 7;
            Ws[kk][c] = Wout[(k0 + kk) * DMODEL + colBase + c];
        }
        __syncthreads();

        #pragma unroll
        for (int kk = 0; kk < 16; kk++) {
            float a[8], b[8];
            *(float4*)&a[0] = *(const float4*)&As[kk][ty * 8];
            *(float4*)&a[4] = *(const float4*)&As[kk][ty * 8 + 4];
            *(float4*)&b[0] = *(const float4*)&Ws[kk][tx * 8];
            *(float4*)&b[4] = *(const float4*)&Ws[kk][tx * 8 + 4];
            #pragma unroll
            for (int i = 0; i < 8; i++)
                #pragma unroll
                for (int j = 0; j < 8; j++)
                    acc[i][j] = fmaf(a[i], b[j], acc[i][j]);
        }
        __syncthreads();
    }

    #pragma unroll
    for (int i = 0; i < 8; i++) {
        int r = rowBase + ty * 8 + i;
        #pragma unroll
        for (int j = 0; j < 8; j++)
            out[r * DMODEL + colBase + tx * 8 + j] = acc[i][j];
    }
}

// ---------------------------------------------------------------------------
extern "C" void kernel_launch(void* const* d_in, const int* in_sizes, int n_in,
                              void* d_out, int out_size)
{
    const float* X  = (const float*)d_in[0];
    const float* Wq = (const float*)d_in[1];
    const float* Wk = (const float*)d_in[2];
    const float* Wv = (const float*)d_in[3];
    const float* Wo = (const float*)d_in[4];
    float* out = (float*)d_out;

    // Not a stream op; safe under graph capture. Needed for 97.5 KB dyn smem.
    cudaFuncSetAttribute(attn_kernel,
                         cudaFuncAttributeMaxDynamicSharedMemorySize, ATTN_SMEM);

    qkv_kernel<<<dim3(24, 64), 256>>>(X, Wq, Wk, Wv);
    attn_kernel<<<dim3(16, BATCH * NHEADS), 256, ATTN_SMEM>>>();
    outproj_kernel<<<dim3(8, 64), 256>>>(Wo, out);
}

// round 10
// speedup vs baseline: 1.0030x; 1.0030x over previous
#include <cuda_runtime.h>
#include <math.h>
#include <cstdint>

#define BATCH   4
#define SEQ     2048
#define DMODEL  1024
#define NHEADS  16
#define DHEAD   64
#define HD      (SEQ * DHEAD)          // per (b,h) plane: 131072

typedef unsigned long long ull;

// Scratch (allocation-free rule: __device__ globals). 32 MB each.
__device__ float g_Q[BATCH * NHEADS * SEQ * DHEAD];
__device__ float g_K[BATCH * NHEADS * SEQ * DHEAD];
__device__ float g_V[BATCH * NHEADS * SEQ * DHEAD];
__device__ float g_O[BATCH * NHEADS * SEQ * DHEAD];

// ---- packed f32x2 helpers (sm_100-family PTX, NOT 'a'-gated) --------------
#define FMA2(d, a, b) \
    asm("fma.rn.f32x2 %0, %1, %2, %0;" : "+l"(d) : "l"(a), "l"(b))
#define MUL2(d, a, b) \
    asm("mul.rn.f32x2 %0, %1, %2;" : "=l"(d) : "l"(a), "l"(b))
#define PACK2(r, lo, hi) \
    asm("mov.b64 %0, {%1, %2};" : "=l"(r) : "f"(lo), "f"(hi))
#define UNPACK2(lo, hi, r) \
    asm("mov.b64 {%0, %1}, %2;" : "=f"(lo), "=f"(hi) : "l"(r))

__device__ __forceinline__ float ex2f(float x) {
    float y;
    asm("ex2.approx.f32 %0, %1;" : "=f"(y) : "f"(x));
    return y;
}

// ---------------------------------------------------------------------------
// Kernel 1: fused QKV projection with f32x2 accumulation.
// C[8192, 3072] = X[8192,1024] * [Wq|Wk|Wv] -> g_Q/g_K/g_V in [b,h,s,d].
// 128x128x16 tile, 256 threads, 8 rows x 4 col-pairs per thread.
// ---------------------------------------------------------------------------
__global__ __launch_bounds__(256) void qkv_kernel(
    const float* __restrict__ X,
    const float* __restrict__ Wq,
    const float* __restrict__ Wk,
    const float* __restrict__ Wv)
{
    __shared__ float Xs[16][132];
    __shared__ float Ws[16][132];

    const int t  = threadIdx.x;
    const int tx = t & 15;
    const int ty = t >> 4;
    const int rowBase = blockIdx.y * 128;
    const int colBase = blockIdx.x * 128;
    const int which   = colBase >> 10;      // 0=Q 1=K 2=V
    const int cB      = colBase & 1023;

    const float* __restrict__ W = (which == 0) ? Wq : (which == 1) ? Wk : Wv;
    float* __restrict__ dstBuf   = (which == 0) ? g_Q : (which == 1) ? g_K : g_V;

    ull acc2[8][4];
    #pragma unroll
    for (int i = 0; i < 8; i++)
        #pragma unroll
        for (int j = 0; j < 4; j++) acc2[i][j] = 0ull;

    for (int k0 = 0; k0 < DMODEL; k0 += 16) {
        #pragma unroll
        for (int i = 0; i < 8; i++) {
            int idx = t + i * 256;
            int kk = idx & 15, r = idx >> 4;
            Xs[kk][r] = X[(rowBase + r) * DMODEL + k0 + kk];
        }
        #pragma unroll
        for (int i = 0; i < 8; i++) {
            int idx = t + i * 256;
            int c = idx & 127, kk = idx >> 7;
            int col = cB + c;
            int h = col >> 6, d = col & 63;
            Ws[kk][c] = W[h * (DMODEL * DHEAD) + (k0 + kk) * DHEAD + d];
        }
        __syncthreads();

        #pragma unroll
        for (int kk = 0; kk < 16; kk++) {
            float a[8], b[8];
            *(float4*)&a[0] = *(const float4*)&Xs[kk][ty * 8];
            *(float4*)&a[4] = *(const float4*)&Xs[kk][ty * 8 + 4];
            *(float4*)&b[0] = *(const float4*)&Ws[kk][tx * 8];
            *(float4*)&b[4] = *(const float4*)&Ws[kk][tx * 8 + 4];
            ull a2[8], b2[4];
            #pragma unroll
            for (int i = 0; i < 8; i++) PACK2(a2[i], a[i], a[i]);
            #pragma unroll
            for (int j = 0; j < 4; j++) PACK2(b2[j], b[2 * j], b[2 * j + 1]);
            #pragma unroll
            for (int i = 0; i < 8; i++)
                #pragma unroll
                for (int j = 0; j < 4; j++)
                    FMA2(acc2[i][j], a2[i], b2[j]);
        }
        __syncthreads();
    }

    #pragma unroll
    for (int i = 0; i < 8; i++) {
        int r  = rowBase + ty * 8 + i;
        int bb = r >> 11;
        int s  = r & 2047;
        #pragma unroll
        for (int j = 0; j < 4; j++) {
            float lo, hi;
            UNPACK2(lo, hi, acc2[i][j]);
            int col0 = cB + tx * 8 + 2 * j;
            int h0 = col0 >> 6, d0 = col0 & 63;
            dstBuf[((bb * NHEADS + h0) * SEQ + s) * DHEAD + d0] = lo;
            int col1 = col0 + 1;
            int h1 = col1 >> 6, d1 = col1 & 63;
            dstBuf[((bb * NHEADS + h1) * SEQ + s) * DHEAD + d1] = hi;
        }
    }
}

// ---------------------------------------------------------------------------
// Kernel 2: causal flash attention with f32x2 reduction pairing.
// QK^T pairs over d (Qs/Ks row-major, stride 66 -> aligned LDS.64);
// P*V pairs over c (V stored transposed [d][c] so c-pairs are contiguous).
// Softmax in log2 domain with ex2.approx.
// ---------------------------------------------------------------------------
#define STR 66
#define ATTN_SMEM ((128 * STR + 64 * STR + 64 * STR + 128 * STR) * 4)  // 101376 B

__global__ __launch_bounds__(256) void attn_kernel()
{
    extern __shared__ float smf[];
    float* Qs  = smf;                       // [128][66] row-major (s, d)
    float* Ks  = Qs + 128 * STR;            // [64][66]  row-major (c, d)
    float* VsT = Ks + 64 * STR;             // [64][66]  TRANSPOSED (d, c)
    float* Ps  = VsT + 64 * STR;            // [128][66] (r, c)

    const int t  = threadIdx.x;
    const int tx = t & 7;
    const int ty = t >> 3;
    const int qt = (gridDim.x - 1) - blockIdx.x;   // longest blocks first
    const int bh = blockIdx.y;

    const float* __restrict__ Qp = g_Q + bh * HD;
    const float* __restrict__ Kp = g_K + bh * HD;
    const float* __restrict__ Vp = g_V + bh * HD;

    // scores pre-scaled into log2 domain: s * (1/8) * log2(e)
    const float SCALE = 0.125f * 1.4426950408889634f;

    #pragma unroll
    for (int i = 0; i < 8; i++) {
        int idx = t + i * 256;
        int r = idx >> 4, d4 = (idx & 15) * 4;
        float4 v = *(const float4*)&Qp[(qt * 128 + r) * DHEAD + d4];
        Qs[r * STR + d4 + 0] = v.x;  Qs[r * STR + d4 + 1] = v.y;
        Qs[r * STR + d4 + 2] = v.z;  Qs[r * STR + d4 + 3] = v.w;
    }

    float mrow[4], lrow[4];
    ull Oacc2[4][8];
    #pragma unroll
    for (int i = 0; i < 4; i++) {
        mrow[i] = -INFINITY;
        lrow[i] = 0.0f;
        #pragma unroll
        for (int j = 0; j < 8; j++) Oacc2[i][j] = 0ull;
    }

    const int nkt = 2 * qt + 2;
    const int qr0 = qt * 128 + ty * 4;

    for (int jt = 0; jt < nkt; jt++) {
        // K row-major, V transposed
        #pragma unroll
        for (int i = 0; i < 4; i++) {
            int idx = t + i * 256;
            int c = idx >> 4, d4 = (idx & 15) * 4;
            float4 kv = *(const float4*)&Kp[(jt * 64 + c) * DHEAD + d4];
            float4 vv = *(const float4*)&Vp[(jt * 64 + c) * DHEAD + d4];
            Ks[c * STR + d4 + 0] = kv.x;  Ks[c * STR + d4 + 1] = kv.y;
            Ks[c * STR + d4 + 2] = kv.z;  Ks[c * STR + d4 + 3] = kv.w;
            VsT[(d4 + 0) * STR + c] = vv.x;  VsT[(d4 + 1) * STR + c] = vv.y;
            VsT[(d4 + 2) * STR + c] = vv.z;  VsT[(d4 + 3) * STR + c] = vv.w;
        }
        __syncthreads();

        // S = Q K^T, paired over d
        ull sc2[4][8];
        #pragma unroll
        for (int i = 0; i < 4; i++)
            #pragma unroll
            for (int j = 0; j < 8; j++) sc2[i][j] = 0ull;

        #pragma unroll 8
        for (int dp = 0; dp < 32; dp++) {
            ull q2[4], k2[8];
            #pragma unroll
            for (int i = 0; i < 4; i++)
                q2[i] = *(const ull*)&Qs[(ty * 4 + i) * STR + 2 * dp];
            #pragma unroll
            for (int j = 0; j < 8; j++)
                k2[j] = *(const ull*)&Ks[(tx + 8 * j) * STR + 2 * dp];
            #pragma unroll
            for (int i = 0; i < 4; i++)
                #pragma unroll
                for (int j = 0; j < 8; j++)
                    FMA2(sc2[i][j], q2[i], k2[j]);
        }

        // horizontal add + scale + causal mask + online softmax (log2 domain)
        #pragma unroll
        for (int i = 0; i < 4; i++) {
            const int qr = qr0 + i;
            float s[8];
            float pm = -INFINITY;
            #pragma unroll
            for (int j = 0; j < 8; j++) {
                float lo, hi;
                UNPACK2(lo, hi, sc2[i][j]);
                float v = (lo + hi) * SCALE;
                int kc = jt * 64 + tx + 8 * j;
                v = (kc <= qr) ? v : -INFINITY;
                s[j] = v;
                pm = fmaxf(pm, v);
            }
            pm = fmaxf(pm, __shfl_xor_sync(0xffffffffu, pm, 1));
            pm = fmaxf(pm, __shfl_xor_sync(0xffffffffu, pm, 2));
            pm = fmaxf(pm, __shfl_xor_sync(0xffffffffu, pm, 4));

            float newm = fmaxf(mrow[i], pm);
            float corr = ex2f(mrow[i] - newm);     // 0 on first tile
            mrow[i] = newm;

            float psum = 0.0f;
            #pragma unroll
            for (int j = 0; j < 8; j++) {
                float p = ex2f(s[j] - newm);       // masked -> 0
                s[j] = p;
                psum += p;
            }
            psum += __shfl_xor_sync(0xffffffffu, psum, 1);
            psum += __shfl_xor_sync(0xffffffffu, psum, 2);
            psum += __shfl_xor_sync(0xffffffffu, psum, 4);

            lrow[i] = lrow[i] * corr + psum;
            ull corr2;
            PACK2(corr2, corr, corr);
            #pragma unroll
            for (int j = 0; j < 8; j++) MUL2(Oacc2[i][j], Oacc2[i][j], corr2);

            #pragma unroll
            for (int j = 0; j < 8; j++)
                Ps[(ty * 4 + i) * STR + (tx + 8 * j)] = s[j];
        }
        __syncthreads();

        // O += P * V, paired over c (VsT makes c-pairs contiguous)
        #pragma unroll 8
        for (int cp = 0; cp < 32; cp++) {
            ull p2[4], v2[8];
            #pragma unroll
            for (int i = 0; i < 4; i++)
                p2[i] = *(const ull*)&Ps[(ty * 4 + i) * STR + 2 * cp];
            #pragma unroll
            for (int j = 0; j < 8; j++)
                v2[j] = *(const ull*)&VsT[(tx + 8 * j) * STR + 2 * cp];
            #pragma unroll
            for (int i = 0; i < 4; i++)
                #pragma unroll
                for (int j = 0; j < 8; j++)
                    FMA2(Oacc2[i][j], p2[i], v2[j]);
        }
        __syncthreads();   // protect tiles before next iteration
    }

    // Normalize (horizontal add folds the c-parity halves) and write [b,h,s,d]
    float* __restrict__ Op = g_O + bh * HD;
    #pragma unroll
    for (int i = 0; i < 4; i++) {
        float inv = 1.0f / lrow[i];
        int qr = qr0 + i;
        #pragma unroll
        for (int j = 0; j < 8; j++) {
            float lo, hi;
            UNPACK2(lo, hi, Oacc2[i][j]);
            Op[qr * DHEAD + (tx + 8 * j)] = (lo + hi) * inv;
        }
    }
}

// ---------------------------------------------------------------------------
// Kernel 3: output projection with f32x2 accumulation.
// out[8192,1024] = concat(g_O)[8192,1024] * Wout.
// ---------------------------------------------------------------------------
__global__ __launch_bounds__(256) void outproj_kernel(
    const float* __restrict__ Wout,
    float* __restrict__ out)
{
    __shared__ float As[16][132];
    __shared__ float Ws[16][132];

    const int t  = threadIdx.x;
    const int tx = t & 15;
    const int ty = t >> 4;
    const int rowBase = blockIdx.y * 128;
    const int colBase = blockIdx.x * 128;

    ull acc2[8][4];
    #pragma unroll
    for (int i = 0; i < 8; i++)
        #pragma unroll
        for (int j = 0; j < 4; j++) acc2[i][j] = 0ull;

    for (int k0 = 0; k0 < DMODEL; k0 += 16) {
        const int h = k0 >> 6;
        #pragma unroll
        for (int i = 0; i < 8; i++) {
            int idx = t + i * 256;
            int kk = idx & 15, r = idx >> 4;
            int d  = (k0 + kk) & 63;
            int rr = rowBase + r;
            int bb = rr >> 11, s = rr & 2047;
            As[kk][r] = g_O[((bb * NHEADS + h) * SEQ + s) * DHEAD + d];
        }
        #pragma unroll
        for (int i = 0; i < 8; i++) {
            int idx = t + i * 256;
            int c = idx & 127, kk = idx >> 7;
            Ws[kk][c] = Wout[(k0 + kk) * DMODEL + colBase + c];
        }
        __syncthreads();

        #pragma unroll
        for (int kk = 0; kk < 16; kk++) {
            float a[8], b[8];
            *(float4*)&a[0] = *(const float4*)&As[kk][ty * 8];
            *(float4*)&a[4] = *(const float4*)&As[kk][ty * 8 + 4];
            *(float4*)&b[0] = *(const float4*)&Ws[kk][tx * 8];
            *(float4*)&b[4] = *(const float4*)&Ws[kk][tx * 8 + 4];
            ull a2[8], b2[4];
            #pragma unroll
            for (int i = 0; i < 8; i++) PACK2(a2[i], a[i], a[i]);
            #pragma unroll
            for (int j = 0; j < 4; j++) PACK2(b2[j], b[2 * j], b[2 * j + 1]);
            #pragma unroll
            for (int i = 0; i < 8; i++)
                #pragma unroll
                for (int j = 0; j < 4; j++)
                    FMA2(acc2[i][j], a2[i], b2[j]);
        }
        __syncthreads();
    }

    #pragma unroll
    for (int i = 0; i < 8; i++) {
        int r = rowBase + ty * 8 + i;
        #pragma unroll
        for (int j = 0; j < 4; j++) {
            float lo, hi;
            UNPACK2(lo, hi, acc2[i][j]);
            out[r * DMODEL + colBase + tx * 8 + 2 * j]     = lo;
            out[r * DMODEL + colBase + tx * 8 + 2 * j + 1] = hi;
        }
    }
}

// ---------------------------------------------------------------------------
extern "C" void kernel_launch(void* const* d_in, const int* in_sizes, int n_in,
                              void* d_out, int out_size)
{
    const float* X  = (const float*)d_in[0];
    const float* Wq = (const float*)d_in[1];
    const float* Wk = (const float*)d_in[2];
    const float* Wv = (const float*)d_in[3];
    const float* Wo = (const float*)d_in[4];
    float* out = (float*)d_out;

    cudaFuncSetAttribute(attn_kernel,
                         cudaFuncAttributeMaxDynamicSharedMemorySize, ATTN_SMEM);

    qkv_kernel<<<dim3(24, 64), 256>>>(X, Wq, Wk, Wv);
    attn_kernel<<<dim3(16, BATCH * NHEADS), 256, ATTN_SMEM>>>();
    outproj_kernel<<<dim3(8, 64), 256>>>(Wo, out);
}

// round 14
// speedup vs baseline: 1.0086x; 1.0056x over previous
#include <cuda_runtime.h>
#include <math.h>
#include <cstdint>

#define BATCH   4
#define SEQ     2048
#define DMODEL  1024
#define NHEADS  16
#define DHEAD   64
#define HD      (SEQ * DHEAD)          // per (b,h) plane: 131072

typedef unsigned long long ull;

// Scratch (allocation-free rule: __device__ globals). 32 MB each.
__device__ float g_Q[BATCH * NHEADS * SEQ * DHEAD];
__device__ float g_K[BATCH * NHEADS * SEQ * DHEAD];
__device__ float g_V[BATCH * NHEADS * SEQ * DHEAD];
__device__ float g_O[BATCH * NHEADS * SEQ * DHEAD];

// ---- packed f32x2 helpers (sm_100-family PTX, NOT 'a'-gated) --------------
#define FMA2(d, a, b) \
    asm("fma.rn.f32x2 %0, %1, %2, %0;" : "+l"(d) : "l"(a), "l"(b))
#define MUL2(d, a, b) \
    asm("mul.rn.f32x2 %0, %1, %2;" : "=l"(d) : "l"(a), "l"(b))
#define PACK2(r, lo, hi) \
    asm("mov.b64 %0, {%1, %2};" : "=l"(r) : "f"(lo), "f"(hi))
#define UNPACK2(lo, hi, r) \
    asm("mov.b64 {%0, %1}, %2;" : "=f"(lo), "=f"(hi) : "l"(r))

__device__ __forceinline__ float ex2f(float x) {
    float y;
    asm("ex2.approx.f32 %0, %1;" : "=f"(y) : "f"(x));
    return y;
}

// ---- cp.async helpers (Ampere+) -------------------------------------------
__device__ __forceinline__ void cp16(void* dst, const void* src) {
    uint32_t d;
    asm("{ .reg .u64 t; cvta.to.shared.u64 t, %1; cvt.u32.u64 %0, t; }"
        : "=r"(d) : "l"(dst));
    asm volatile("cp.async.cg.shared.global [%0], [%1], 16;"
                 :: "r"(d), "l"(src) : "memory");
}
#define CP_COMMIT()  asm volatile("cp.async.commit_group;" ::: "memory")
#define CP_WAIT1()   asm volatile("cp.async.wait_group 1;" ::: "memory")
#define CP_WAIT0()   asm volatile("cp.async.wait_group 0;" ::: "memory")

// ---------------------------------------------------------------------------
// Kernel 1: fused QKV projection, cp.async 2-stage pipeline + f32x2 FMA.
// C[8192, 3072] = X[8192,1024] * [Wq|Wk|Wv] -> g_Q/g_K/g_V in [b,h,s,d].
// 128x128x16 tile, 256 threads, 8 rows x 4 col-pairs per thread.
// ---------------------------------------------------------------------------
#define XS_STR 20   // 80 B rows, 16B-aligned

__global__ __launch_bounds__(256) void qkv_kernel(
    const float* __restrict__ X,
    const float* __restrict__ Wq,
    const float* __restrict__ Wk,
    const float* __restrict__ Wv)
{
    __shared__ __align__(16) float Xs[2][128][XS_STR];   // row-major [r][kk]
    __shared__ __align__(16) float Ws[2][16][132];       // [kk][c]

    const int t  = threadIdx.x;
    const int tx = t & 15;
    const int ty = t >> 4;
    const int rowBase = blockIdx.y * 128;
    const int colBase = blockIdx.x * 128;
    const int which   = colBase >> 10;      // 0=Q 1=K 2=V
    const int cB      = colBase & 1023;

    const float* __restrict__ W = (which == 0) ? Wq : (which == 1) ? Wk : Wv;
    float* __restrict__ dstBuf   = (which == 0) ? g_Q : (which == 1) ? g_K : g_V;

    ull acc2[8][4];
    #pragma unroll
    for (int i = 0; i < 8; i++)
        #pragma unroll
        for (int j = 0; j < 4; j++) acc2[i][j] = 0ull;

    // issue one k-tile (16 wide) into stage st
    auto issue = [&](int kt, int st) {
        const int k0 = kt * 16;
        #pragma unroll
        for (int i = 0; i < 2; i++) {                 // X: 512 16B chunks
            int idx = t + i * 256;
            int r = idx >> 2, c4 = (idx & 3) * 4;
            cp16(&Xs[st][r][c4], &X[(rowBase + r) * DMODEL + k0 + c4]);
        }
        #pragma unroll
        for (int i = 0; i < 2; i++) {                 // W: 512 16B chunks
            int idx = t + i * 256;
            int kk = idx >> 5, c4 = (idx & 31) * 4;
            int col = cB + c4;
            int h = col >> 6, d = col & 63;
            cp16(&Ws[st][kk][c4], &W[h * (DMODEL * DHEAD) + (k0 + kk) * DHEAD + d]);
        }
        CP_COMMIT();
    };

    issue(0, 0);
    for (int kt = 0; kt < 64; kt++) {
        const int st = kt & 1;
        if (kt < 63) { issue(kt + 1, st ^ 1); CP_WAIT1(); }
        else         { CP_WAIT0(); }
        __syncthreads();

        #pragma unroll
        for (int kk = 0; kk < 16; kk++) {
            float a[8], b[8];
            #pragma unroll
            for (int i = 0; i < 8; i++) a[i] = Xs[st][ty * 8 + i][kk];
            *(float4*)&b[0] = *(const float4*)&Ws[st][kk][tx * 8];
            *(float4*)&b[4] = *(const float4*)&Ws[st][kk][tx * 8 + 4];
            ull a2[8], b2[4];
            #pragma unroll
            for (int i = 0; i < 8; i++) PACK2(a2[i], a[i], a[i]);
            #pragma unroll
            for (int j = 0; j < 4; j++) PACK2(b2[j], b[2 * j], b[2 * j + 1]);
            #pragma unroll
            for (int i = 0; i < 8; i++)
                #pragma unroll
                for (int j = 0; j < 4; j++)
                    FMA2(acc2[i][j], a2[i], b2[j]);
        }
        __syncthreads();
    }

    #pragma unroll
    for (int i = 0; i < 8; i++) {
        int r  = rowBase + ty * 8 + i;
        int bb = r >> 11;
        int s  = r & 2047;
        #pragma unroll
        for (int j = 0; j < 4; j++) {
            float lo, hi;
            UNPACK2(lo, hi, acc2[i][j]);
            int col0 = cB + tx * 8 + 2 * j;
            int h0 = col0 >> 6, d0 = col0 & 63;
            dstBuf[((bb * NHEADS + h0) * SEQ + s) * DHEAD + d0] = lo;
            int col1 = col0 + 1;
            int h1 = col1 >> 6, d1 = col1 & 63;
            dstBuf[((bb * NHEADS + h1) * SEQ + s) * DHEAD + d1] = hi;
        }
    }
}

// ---------------------------------------------------------------------------
// Kernel 2: causal flash attention, f32x2 reduction pairing + register
// prefetch of next K/V tiles (LDG issued right after tile-ready sync so
// latency spans the whole S-compute phase).
// ---------------------------------------------------------------------------
#define STR 66
#define ATTN_SMEM ((128 * STR + 64 * STR + 64 * STR + 128 * STR) * 4)  // 101376 B

__global__ __launch_bounds__(256) void attn_kernel()
{
    extern __shared__ float smf[];
    float* Qs  = smf;                       // [128][66] (s, d)
    float* Ks  = Qs + 128 * STR;            // [64][66]  (c, d)
    float* VsT = Ks + 64 * STR;             // [64][66]  TRANSPOSED (d, c)
    float* Ps  = VsT + 64 * STR;            // [128][66] (r, c)

    const int t  = threadIdx.x;
    const int tx = t & 7;
    const int ty = t >> 3;
    const int qt = (gridDim.x - 1) - blockIdx.x;   // longest blocks first
    const int bh = blockIdx.y;

    const float* __restrict__ Qp = g_Q + bh * HD;
    const float* __restrict__ Kp = g_K + bh * HD;
    const float* __restrict__ Vp = g_V + bh * HD;

    const float SCALE = 0.125f * 1.4426950408889634f;   // log2 domain

    #pragma unroll
    for (int i = 0; i < 8; i++) {
        int idx = t + i * 256;
        int r = idx >> 4, d4 = (idx & 15) * 4;
        float4 v = *(const float4*)&Qp[(qt * 128 + r) * DHEAD + d4];
        Qs[r * STR + d4 + 0] = v.x;  Qs[r * STR + d4 + 1] = v.y;
        Qs[r * STR + d4 + 2] = v.z;  Qs[r * STR + d4 + 3] = v.w;
    }

    float mrow[4], lrow[4];
    ull Oacc2[4][8];
    #pragma unroll
    for (int i = 0; i < 4; i++) {
        mrow[i] = -INFINITY;
        lrow[i] = 0.0f;
        #pragma unroll
        for (int j = 0; j < 8; j++) Oacc2[i][j] = 0ull;
    }

    const int nkt = 2 * qt + 2;
    const int qr0 = qt * 128 + ty * 4;

    // per-thread fixed chunk coordinates for K/V tile loads
    float4 kreg[4], vreg[4];
    auto ldKV = [&](int jt) {
        #pragma unroll
        for (int i = 0; i < 4; i++) {
            int idx = t + i * 256;
            int c = idx >> 4, d4 = (idx & 15) * 4;
            kreg[i] = *(const float4*)&Kp[(jt * 64 + c) * DHEAD + d4];
            vreg[i] = *(const float4*)&Vp[(jt * 64 + c) * DHEAD + d4];
        }
    };
    ldKV(0);

    for (int jt = 0; jt < nkt; jt++) {
        // store prefetched tiles: K row-major, V transposed
        #pragma unroll
        for (int i = 0; i < 4; i++) {
            int idx = t + i * 256;
            int c = idx >> 4, d4 = (idx & 15) * 4;
            Ks[c * STR + d4 + 0] = kreg[i].x;  Ks[c * STR + d4 + 1] = kreg[i].y;
            Ks[c * STR + d4 + 2] = kreg[i].z;  Ks[c * STR + d4 + 3] = kreg[i].w;
            VsT[(d4 + 0) * STR + c] = vreg[i].x;  VsT[(d4 + 1) * STR + c] = vreg[i].y;
            VsT[(d4 + 2) * STR + c] = vreg[i].z;  VsT[(d4 + 3) * STR + c] = vreg[i].w;
        }
        __syncthreads();

        if (jt + 1 < nkt) ldKV(jt + 1);    // prefetch; latency spans S-compute

        // S = Q K^T, paired over d
        ull sc2[4][8];
        #pragma unroll
        for (int i = 0; i < 4; i++)
            #pragma unroll
            for (int j = 0; j < 8; j++) sc2[i][j] = 0ull;

        #pragma unroll 8
        for (int dp = 0; dp < 32; dp++) {
            ull q2[4], k2[8];
            #pragma unroll
            for (int i = 0; i < 4; i++)
                q2[i] = *(const ull*)&Qs[(ty * 4 + i) * STR + 2 * dp];
            #pragma unroll
            for (int j = 0; j < 8; j++)
                k2[j] = *(const ull*)&Ks[(tx + 8 * j) * STR + 2 * dp];
            #pragma unroll
            for (int i = 0; i < 4; i++)
                #pragma unroll
                for (int j = 0; j < 8; j++)
                    FMA2(sc2[i][j], q2[i], k2[j]);
        }

        // horizontal add + scale + causal mask + online softmax (log2 domain)
        #pragma unroll
        for (int i = 0; i < 4; i++) {
            const int qr = qr0 + i;
            float s[8];
            float pm = -INFINITY;
            #pragma unroll
            for (int j = 0; j < 8; j++) {
                float lo, hi;
                UNPACK2(lo, hi, sc2[i][j]);
                float v = (lo + hi) * SCALE;
                int kc = jt * 64 + tx + 8 * j;
                v = (kc <= qr) ? v : -INFINITY;
                s[j] = v;
                pm = fmaxf(pm, v);
            }
            pm = fmaxf(pm, __shfl_xor_sync(0xffffffffu, pm, 1));
            pm = fmaxf(pm, __shfl_xor_sync(0xffffffffu, pm, 2));
            pm = fmaxf(pm, __shfl_xor_sync(0xffffffffu, pm, 4));

            float newm = fmaxf(mrow[i], pm);
            float corr = ex2f(mrow[i] - newm);
            mrow[i] = newm;

            float psum = 0.0f;
            #pragma unroll
            for (int j = 0; j < 8; j++) {
                float p = ex2f(s[j] - newm);
                s[j] = p;
                psum += p;
            }
            psum += __shfl_xor_sync(0xffffffffu, psum, 1);
            psum += __shfl_xor_sync(0xffffffffu, psum, 2);
            psum += __shfl_xor_sync(0xffffffffu, psum, 4);

            lrow[i] = lrow[i] * corr + psum;
            ull corr2;
            PACK2(corr2, corr, corr);
            #pragma unroll
            for (int j = 0; j < 8; j++) MUL2(Oacc2[i][j], Oacc2[i][j], corr2);

            #pragma unroll
            for (int j = 0; j < 8; j++)
                Ps[(ty * 4 + i) * STR + (tx + 8 * j)] = s[j];
        }
        __syncthreads();

        // O += P * V, paired over c
        #pragma unroll 8
        for (int cp = 0; cp < 32; cp++) {
            ull p2[4], v2[8];
            #pragma unroll
            for (int i = 0; i < 4; i++)
                p2[i] = *(const ull*)&Ps[(ty * 4 + i) * STR + 2 * cp];
            #pragma unroll
            for (int j = 0; j < 8; j++)
                v2[j] = *(const ull*)&VsT[(tx + 8 * j) * STR + 2 * cp];
            #pragma unroll
            for (int i = 0; i < 4; i++)
                #pragma unroll
                for (int j = 0; j < 8; j++)
                    FMA2(Oacc2[i][j], p2[i], v2[j]);
        }
        __syncthreads();
    }

    float* __restrict__ Op = g_O + bh * HD;
    #pragma unroll
    for (int i = 0; i < 4; i++) {
        float inv = 1.0f / lrow[i];
        int qr = qr0 + i;
        #pragma unroll
        for (int j = 0; j < 8; j++) {
            float lo, hi;
            UNPACK2(lo, hi, Oacc2[i][j]);
            Op[qr * DHEAD + (tx + 8 * j)] = (lo + hi) * inv;
        }
    }
}

// ---------------------------------------------------------------------------
// Kernel 3: output projection, cp.async 2-stage pipeline + f32x2 FMA.
// out[8192,1024] = concat(g_O)[8192,1024] * Wout.
// ---------------------------------------------------------------------------
__global__ __launch_bounds__(256) void outproj_kernel(
    const float* __restrict__ Wout,
    float* __restrict__ out)
{
    __shared__ __align__(16) float As[2][128][XS_STR];   // [r][kk]
    __shared__ __align__(16) float Ws[2][16][132];       // [kk][c]

    const int t  = threadIdx.x;
    const int tx = t & 15;
    const int ty = t >> 4;
    const int rowBase = blockIdx.y * 128;
    const int colBase = blockIdx.x * 128;

    ull acc2[8][4];
    #pragma unroll
    for (int i = 0; i < 8; i++)
        #pragma unroll
        for (int j = 0; j < 4; j++) acc2[i][j] = 0ull;

    auto issue = [&](int kt, int st) {
        const int k0 = kt * 16;
        const int h = k0 >> 6, dBase = k0 & 63;
        #pragma unroll
        for (int i = 0; i < 2; i++) {                 // A: from g_O, permuted
            int idx = t + i * 256;
            int r = idx >> 2, c4 = (idx & 3) * 4;
            int rr = rowBase + r;
            int bb = rr >> 11, s = rr & 2047;
            cp16(&As[st][r][c4],
                 &g_O[((bb * NHEADS + h) * SEQ + s) * DHEAD + dBase + c4]);
        }
        #pragma unroll
        for (int i = 0; i < 2; i++) {                 // W
            int idx = t + i * 256;
            int kk = idx >> 5, c4 = (idx & 31) * 4;
            cp16(&Ws[st][kk][c4], &Wout[(k0 + kk) * DMODEL + colBase + c4]);
        }
        CP_COMMIT();
    };

    issue(0, 0);
    for (int kt = 0; kt < 64; kt++) {
        const int st = kt & 1;
        if (kt < 63) { issue(kt + 1, st ^ 1); CP_WAIT1(); }
        else         { CP_WAIT0(); }
        __syncthreads();

        #pragma unroll
        for (int kk = 0; kk < 16; kk++) {
            float a[8], b[8];
            #pragma unroll
            for (int i = 0; i < 8; i++) a[i] = As[st][ty * 8 + i][kk];
            *(float4*)&b[0] = *(const float4*)&Ws[st][kk][tx * 8];
            *(float4*)&b[4] = *(const float4*)&Ws[st][kk][tx * 8 + 4];
            ull a2[8], b2[4];
            #pragma unroll
            for (int i = 0; i < 8; i++) PACK2(a2[i], a[i], a[i]);
            #pragma unroll
            for (int j = 0; j < 4; j++) PACK2(b2[j], b[2 * j], b[2 * j + 1]);
            #pragma unroll
            for (int i = 0; i < 8; i++)
                #pragma unroll
                for (int j = 0; j < 4; j++)
                    FMA2(acc2[i][j], a2[i], b2[j]);
        }
        __syncthreads();
    }

    #pragma unroll
    for (int i = 0; i < 8; i++) {
        int r = rowBase + ty * 8 + i;
        #pragma unroll
        for (int j = 0; j < 4; j++) {
            float lo, hi;
            UNPACK2(lo, hi, acc2[i][j]);
            out[r * DMODEL + colBase + tx * 8 + 2 * j]     = lo;
            out[r * DMODEL + colBase + tx * 8 + 2 * j + 1] = hi;
        }
    }
}

// ---------------------------------------------------------------------------
extern "C" void kernel_launch(void* const* d_in, const int* in_sizes, int n_in,
                              void* d_out, int out_size)
{
    const float* X  = (const float*)d_in[0];
    const float* Wq = (const float*)d_in[1];
    const float* Wk = (const float*)d_in[2];
    const float* Wv = (const float*)d_in[3];
    const float* Wo = (const float*)d_in[4];
    float* out = (float*)d_out;

    cudaFuncSetAttribute(attn_kernel,
                         cudaFuncAttributeMaxDynamicSharedMemorySize, ATTN_SMEM);

    qkv_kernel<<<dim3(24, 64), 256>>>(X, Wq, Wk, Wv);
    attn_kernel<<<dim3(16, BATCH * NHEADS), 256, ATTN_SMEM>>>();
    outproj_kernel<<<dim3(8, 64), 256>>>(Wo, out);
}

// round 15
// speedup vs baseline: 1.1694x; 1.1594x over previous
#include <cuda_runtime.h>
#include <math.h>
#include <cstdint>

#define BATCH   4
#define SEQ     2048
#define DMODEL  1024
#define NHEADS  16
#define DHEAD   64
#define HD      (SEQ * DHEAD)          // per (b,h) plane: 131072

typedef unsigned long long ull;

// Scratch (allocation-free rule: __device__ globals).
__device__ float g_Q[BATCH * NHEADS * SEQ * DHEAD];
__device__ float g_K[BATCH * NHEADS * SEQ * DHEAD];
__device__ float g_V[BATCH * NHEADS * SEQ * DHEAD];
__device__ float g_O[BATCH * NHEADS * SEQ * DHEAD];

// tf32-split operand planes (stored as fp32 values already tf32-rounded)
__device__ float g_Xh[8192 * 1024];
__device__ float g_Xl[8192 * 1024];
__device__ float g_Bh[3072 * 1024];    // [n][k] = qkv weights transposed
__device__ float g_Bl[3072 * 1024];
__device__ float g_Oh[8192 * 1024];    // concat(O) rows
__device__ float g_Ol[8192 * 1024];
__device__ float g_WOh[1024 * 1024];   // Wout^T  [n][k]
__device__ float g_WOl[1024 * 1024];

// ---- helpers --------------------------------------------------------------
#define FMA2(d, a, b) \
    asm("fma.rn.f32x2 %0, %1, %2, %0;" : "+l"(d) : "l"(a), "l"(b))
#define MUL2(d, a, b) \
    asm("mul.rn.f32x2 %0, %1, %2;" : "=l"(d) : "l"(a), "l"(b))
#define PACK2(r, lo, hi) \
    asm("mov.b64 %0, {%1, %2};" : "=l"(r) : "f"(lo), "f"(hi))
#define UNPACK2(lo, hi, r) \
    asm("mov.b64 {%0, %1}, %2;" : "=f"(lo), "=f"(hi) : "l"(r))

__device__ __forceinline__ float ex2f(float x) {
    float y;
    asm("ex2.approx.f32 %0, %1;" : "=f"(y) : "f"(x));
    return y;
}

__device__ __forceinline__ void cp16(void* dst, const void* src) {
    uint32_t d;
    asm("{ .reg .u64 t; cvta.to.shared.u64 t, %1; cvt.u32.u64 %0, t; }"
        : "=r"(d) : "l"(dst));
    asm volatile("cp.async.cg.shared.global [%0], [%1], 16;"
                 :: "r"(d), "l"(src) : "memory");
}
#define CP_COMMIT()  asm volatile("cp.async.commit_group;" ::: "memory")
#define CP_WAIT1()   asm volatile("cp.async.wait_group 1;" ::: "memory")
#define CP_WAIT0()   asm volatile("cp.async.wait_group 0;" ::: "memory")

// tf32 split: x = hi + lo, both exactly representable in tf32
__device__ __forceinline__ void tf32_split(float x, float& h, float& l) {
    uint32_t hb;
    asm("cvt.rna.tf32.f32 %0, %1;" : "=r"(hb) : "f"(x));
    h = __uint_as_float(hb);
    float r = x - h;
    uint32_t lb;
    asm("cvt.rna.tf32.f32 %0, %1;" : "=r"(lb) : "f"(r));
    l = __uint_as_float(lb);
}

// m16n8k8 TF32 MMA, fp32 accumulate (sm_80+ PTX, legal at compute_103)
#define MMA_TF32(c, a0, a1, a2, a3, b0, b1)                                  \
    asm volatile("mma.sync.aligned.m16n8k8.row.col.f32.tf32.tf32.f32 "       \
        "{%0,%1,%2,%3}, {%4,%5,%6,%7}, {%8,%9}, {%0,%1,%2,%3};"              \
        : "+f"((c)[0]), "+f"((c)[1]), "+f"((c)[2]), "+f"((c)[3])             \
        : "r"(a0), "r"(a1), "r"(a2), "r"(a3), "r"(b0), "r"(b1))

// ---------------------------------------------------------------------------
// Prep kernels: tf32 hi/lo splits (+ layout permutations)
// ---------------------------------------------------------------------------
__global__ __launch_bounds__(256) void split_x_kernel(const float* __restrict__ X) {
    int i4 = blockIdx.x * 256 + threadIdx.x;       // over 8192*1024/4
    float4 v = *(const float4*)&X[(size_t)i4 * 4];
    float h, l;
    tf32_split(v.x, h, l); g_Xh[i4*4+0] = h; g_Xl[i4*4+0] = l;
    tf32_split(v.y, h, l); g_Xh[i4*4+1] = h; g_Xl[i4*4+1] = l;
    tf32_split(v.z, h, l); g_Xh[i4*4+2] = h; g_Xl[i4*4+2] = l;
    tf32_split(v.w, h, l); g_Xh[i4*4+3] = h; g_Xl[i4*4+3] = l;
}

// g_B[n][k], n = which*1024 + h*64 + d; source W[h][k][d]
__global__ __launch_bounds__(256) void split_wqkv_kernel(
    const float* __restrict__ Wq, const float* __restrict__ Wk,
    const float* __restrict__ Wv) {
    int idx = blockIdx.x * 256 + threadIdx.x;      // over 3072*1024
    int n = idx >> 10, k = idx & 1023;
    int which = n >> 10, h = (n & 1023) >> 6, d = n & 63;
    const float* W = (which == 0) ? Wq : (which == 1) ? Wk : Wv;
    float x = W[h * (DMODEL * DHEAD) + k * DHEAD + d];
    tf32_split(x, g_Bh[idx], g_Bl[idx]);
}

__global__ __launch_bounds__(256) void split_wout_kernel(const float* __restrict__ Wo) {
    int idx = blockIdx.x * 256 + threadIdx.x;      // over 1024*1024
    int n = idx >> 10, k = idx & 1023;
    tf32_split(Wo[k * 1024 + n], g_WOh[idx], g_WOl[idx]);
}

// g_O [b,h,s,d] -> row-major concat [r=8192][m=1024], m = h*64+d
__global__ __launch_bounds__(256) void split_o_kernel() {
    int i4 = blockIdx.x * 256 + threadIdx.x;       // over 8192*1024/4
    int idx = i4 * 4;
    int r = idx >> 10, m = idx & 1023;
    int h = m >> 6, d = m & 63;
    int b = r >> 11, s = r & 2047;
    float4 v = *(const float4*)&g_O[((b * NHEADS + h) * SEQ + s) * DHEAD + d];
    float hh, ll;
    tf32_split(v.x, hh, ll); g_Oh[idx+0] = hh; g_Ol[idx+0] = ll;
    tf32_split(v.y, hh, ll); g_Oh[idx+1] = hh; g_Ol[idx+1] = ll;
    tf32_split(v.z, hh, ll); g_Oh[idx+2] = hh; g_Ol[idx+2] = ll;
    tf32_split(v.w, hh, ll); g_Oh[idx+3] = hh; g_Ol[idx+3] = ll;
}

// ---------------------------------------------------------------------------
// TF32 MMA GEMM: C[128x128/CTA] = A[M,1024] x B[N,1024]^T, 3-segment split
// (Ah*Bh + Ah*Bl + Al*Bh), fp32 accum. 8 warps 2x4, warp tile 64x32.
// k-tile 32, cp.async double buffer. mode 0: scatter to g_Q/K/V; 1: row-major.
// ---------------------------------------------------------------------------
#define GK    32
#define GSTR  36                               // 144 B rows, 16B-aligned
#define GEMM_SMEM (4 * 128 * GSTR * 4)         // A[2]+B[2] = 73728 B

__global__ __launch_bounds__(256) void mma_gemm_kernel(
    const float* __restrict__ A0, const float* __restrict__ A1,
    const float* __restrict__ B0, const float* __restrict__ B1,
    float* __restrict__ outp, int mode)
{
    extern __shared__ float sm[];
    float* smA = sm;                           // [2][128][GSTR]
    float* smB = sm + 2 * 128 * GSTR;          // [2][128][GSTR]

    const int t    = threadIdx.x;
    const int w    = t >> 5, lane = t & 31;
    const int gid  = lane >> 2, tin = lane & 3;
    const int wm   = w >> 2, wn = w & 3;       // 2 x 4 warp grid
    const int rowBase = blockIdx.y * 128;
    const int colBase = blockIdx.x * 128;

    float acc[4][4][4];
    #pragma unroll
    for (int mt = 0; mt < 4; mt++)
        #pragma unroll
        for (int nt = 0; nt < 4; nt++)
            #pragma unroll
            for (int i = 0; i < 4; i++) acc[mt][nt][i] = 0.0f;

    const int nIt = 96;                        // 3 segments x 32 k-tiles

    auto issue = [&](int it, int st) {
        const int seg = it >> 5, k0 = (it & 31) * GK;
        const float* Asrc = (seg == 2) ? A1 : A0;
        const float* Bsrc = (seg == 1) ? B1 : B0;
        #pragma unroll
        for (int i = 0; i < 4; i++) {          // A: 1024 16B chunks
            int idx = t + i * 256;
            int r = idx >> 3, c4 = (idx & 7) * 4;
            cp16(&smA[(st * 128 + r) * GSTR + c4],
                 &Asrc[(size_t)(rowBase + r) * 1024 + k0 + c4]);
        }
        #pragma unroll
        for (int i = 0; i < 4; i++) {          // B: 1024 16B chunks
            int idx = t + i * 256;
            int r = idx >> 3, c4 = (idx & 7) * 4;
            cp16(&smB[(st * 128 + r) * GSTR + c4],
                 &Bsrc[(size_t)(colBase + r) * 1024 + k0 + c4]);
        }
        CP_COMMIT();
    };

    issue(0, 0);
    for (int it = 0; it < nIt; it++) {
        const int st = it & 1;
        if (it + 1 < nIt) { issue(it + 1, st ^ 1); CP_WAIT1(); }
        else              { CP_WAIT0(); }
        __syncthreads();

        const float* As = smA + st * 128 * GSTR;
        const float* Bs = smB + st * 128 * GSTR;

        #pragma unroll
        for (int ks = 0; ks < 4; ks++) {
            const int kc0 = ks * 8 + tin, kc1 = kc0 + 4;
            uint32_t bf[4][2];
            #pragma unroll
            for (int nt = 0; nt < 4; nt++) {
                int n = wn * 32 + nt * 8 + gid;
                bf[nt][0] = __float_as_uint(Bs[n * GSTR + kc0]);
                bf[nt][1] = __float_as_uint(Bs[n * GSTR + kc1]);
            }
            #pragma unroll
            for (int mt = 0; mt < 4; mt++) {
                int r0 = wm * 64 + mt * 16 + gid, r1 = r0 + 8;
                uint32_t a0 = __float_as_uint(As[r0 * GSTR + kc0]);
                uint32_t a1 = __float_as_uint(As[r1 * GSTR + kc0]);
                uint32_t a2 = __float_as_uint(As[r0 * GSTR + kc1]);
                uint32_t a3 = __float_as_uint(As[r1 * GSTR + kc1]);
                #pragma unroll
                for (int nt = 0; nt < 4; nt++)
                    MMA_TF32(acc[mt][nt], a0, a1, a2, a3, bf[nt][0], bf[nt][1]);
            }
        }
        __syncthreads();
    }

    // Epilogue: c0,c1 -> (r0, col0..col0+1); c2,c3 -> (r1, ...)
    if (mode == 0) {
        #pragma unroll
        for (int mt = 0; mt < 4; mt++) {
            int r0 = rowBase + wm * 64 + mt * 16 + gid, r1 = r0 + 8;
            int b0i = r0 >> 11, s0 = r0 & 2047;
            int b1i = r1 >> 11, s1 = r1 & 2047;
            #pragma unroll
            for (int nt = 0; nt < 4; nt++) {
                int col = colBase + wn * 32 + nt * 8 + 2 * tin;
                int which = col >> 10;
                float* dst = (which == 0) ? g_Q : (which == 1) ? g_K : g_V;
                int h = (col & 1023) >> 6, d = col & 63;
                *(float2*)&dst[((b0i * NHEADS + h) * SEQ + s0) * DHEAD + d] =
                    make_float2(acc[mt][nt][0], acc[mt][nt][1]);
                *(float2*)&dst[((b1i * NHEADS + h) * SEQ + s1) * DHEAD + d] =
                    make_float2(acc[mt][nt][2], acc[mt][nt][3]);
            }
        }
    } else {
        #pragma unroll
        for (int mt = 0; mt < 4; mt++) {
            int r0 = rowBase + wm * 64 + mt * 16 + gid, r1 = r0 + 8;
            #pragma unroll
            for (int nt = 0; nt < 4; nt++) {
                int col = colBase + wn * 32 + nt * 8 + 2 * tin;
                *(float2*)&outp[(size_t)r0 * 1024 + col] =
                    make_float2(acc[mt][nt][0], acc[mt][nt][1]);
                *(float2*)&outp[(size_t)r1 * 1024 + col] =
                    make_float2(acc[mt][nt][2], acc[mt][nt][3]);
            }
        }
    }
}

// ---------------------------------------------------------------------------
// Kernel 2: causal flash attention (unchanged from passing R14 kernel)
// ---------------------------------------------------------------------------
#define STR 66
#define ATTN_SMEM ((128 * STR + 64 * STR + 64 * STR + 128 * STR) * 4)  // 101376 B

__global__ __launch_bounds__(256) void attn_kernel()
{
    extern __shared__ float smf[];
    float* Qs  = smf;
    float* Ks  = Qs + 128 * STR;
    float* VsT = Ks + 64 * STR;
    float* Ps  = VsT + 64 * STR;

    const int t  = threadIdx.x;
    const int tx = t & 7;
    const int ty = t >> 3;
    const int qt = (gridDim.x - 1) - blockIdx.x;
    const int bh = blockIdx.y;

    const float* __restrict__ Qp = g_Q + bh * HD;
    const float* __restrict__ Kp = g_K + bh * HD;
    const float* __restrict__ Vp = g_V + bh * HD;

    const float SCALE = 0.125f * 1.4426950408889634f;

    #pragma unroll
    for (int i = 0; i < 8; i++) {
        int idx = t + i * 256;
        int r = idx >> 4, d4 = (idx & 15) * 4;
        float4 v = *(const float4*)&Qp[(qt * 128 + r) * DHEAD + d4];
        Qs[r * STR + d4 + 0] = v.x;  Qs[r * STR + d4 + 1] = v.y;
        Qs[r * STR + d4 + 2] = v.z;  Qs[r * STR + d4 + 3] = v.w;
    }

    float mrow[4], lrow[4];
    ull Oacc2[4][8];
    #pragma unroll
    for (int i = 0; i < 4; i++) {
        mrow[i] = -INFINITY;
        lrow[i] = 0.0f;
        #pragma unroll
        for (int j = 0; j < 8; j++) Oacc2[i][j] = 0ull;
    }

    const int nkt = 2 * qt + 2;
    const int qr0 = qt * 128 + ty * 4;

    float4 kreg[4], vreg[4];
    auto ldKV = [&](int jt) {
        #pragma unroll
        for (int i = 0; i < 4; i++) {
            int idx = t + i * 256;
            int c = idx >> 4, d4 = (idx & 15) * 4;
            kreg[i] = *(const float4*)&Kp[(jt * 64 + c) * DHEAD + d4];
            vreg[i] = *(const float4*)&Vp[(jt * 64 + c) * DHEAD + d4];
        }
    };
    ldKV(0);

    for (int jt = 0; jt < nkt; jt++) {
        #pragma unroll
        for (int i = 0; i < 4; i++) {
            int idx = t + i * 256;
            int c = idx >> 4, d4 = (idx & 15) * 4;
            Ks[c * STR + d4 + 0] = kreg[i].x;  Ks[c * STR + d4 + 1] = kreg[i].y;
            Ks[c * STR + d4 + 2] = kreg[i].z;  Ks[c * STR + d4 + 3] = kreg[i].w;
            VsT[(d4 + 0) * STR + c] = vreg[i].x;  VsT[(d4 + 1) * STR + c] = vreg[i].y;
            VsT[(d4 + 2) * STR + c] = vreg[i].z;  VsT[(d4 + 3) * STR + c] = vreg[i].w;
        }
        __syncthreads();

        if (jt + 1 < nkt) ldKV(jt + 1);

        ull sc2[4][8];
        #pragma unroll
        for (int i = 0; i < 4; i++)
            #pragma unroll
            for (int j = 0; j < 8; j++) sc2[i][j] = 0ull;

        #pragma unroll 8
        for (int dp = 0; dp < 32; dp++) {
            ull q2[4], k2[8];
            #pragma unroll
            for (int i = 0; i < 4; i++)
                q2[i] = *(const ull*)&Qs[(ty * 4 + i) * STR + 2 * dp];
            #pragma unroll
            for (int j = 0; j < 8; j++)
                k2[j] = *(const ull*)&Ks[(tx + 8 * j) * STR + 2 * dp];
            #pragma unroll
            for (int i = 0; i < 4; i++)
                #pragma unroll
                for (int j = 0; j < 8; j++)
                    FMA2(sc2[i][j], q2[i], k2[j]);
        }

        #pragma unroll
        for (int i = 0; i < 4; i++) {
            const int qr = qr0 + i;
            float s[8];
            float pm = -INFINITY;
            #pragma unroll
            for (int j = 0; j < 8; j++) {
                float lo, hi;
                UNPACK2(lo, hi, sc2[i][j]);
                float v = (lo + hi) * SCALE;
                int kc = jt * 64 + tx + 8 * j;
                v = (kc <= qr) ? v : -INFINITY;
                s[j] = v;
                pm = fmaxf(pm, v);
            }
            pm = fmaxf(pm, __shfl_xor_sync(0xffffffffu, pm, 1));
            pm = fmaxf(pm, __shfl_xor_sync(0xffffffffu, pm, 2));
            pm = fmaxf(pm, __shfl_xor_sync(0xffffffffu, pm, 4));

            float newm = fmaxf(mrow[i], pm);
            float corr = ex2f(mrow[i] - newm);
            mrow[i] = newm;

            float psum = 0.0f;
            #pragma unroll
            for (int j = 0; j < 8; j++) {
                float p = ex2f(s[j] - newm);
                s[j] = p;
                psum += p;
            }
            psum += __shfl_xor_sync(0xffffffffu, psum, 1);
            psum += __shfl_xor_sync(0xffffffffu, psum, 2);
            psum += __shfl_xor_sync(0xffffffffu, psum, 4);

            lrow[i] = lrow[i] * corr + psum;
            ull corr2;
            PACK2(corr2, corr, corr);
            #pragma unroll
            for (int j = 0; j < 8; j++) MUL2(Oacc2[i][j], Oacc2[i][j], corr2);

            #pragma unroll
            for (int j = 0; j < 8; j++)
                Ps[(ty * 4 + i) * STR + (tx + 8 * j)] = s[j];
        }
        __syncthreads();

        #pragma unroll 8
        for (int cp = 0; cp < 32; cp++) {
            ull p2[4], v2[8];
            #pragma unroll
            for (int i = 0; i < 4; i++)
                p2[i] = *(const ull*)&Ps[(ty * 4 + i) * STR + 2 * cp];
            #pragma unroll
            for (int j = 0; j < 8; j++)
                v2[j] = *(const ull*)&VsT[(tx + 8 * j) * STR + 2 * cp];
            #pragma unroll
            for (int i = 0; i < 4; i++)
                #pragma unroll
                for (int j = 0; j < 8; j++)
                    FMA2(Oacc2[i][j], p2[i], v2[j]);
        }
        __syncthreads();
    }

    float* __restrict__ Op = g_O + bh * HD;
    #pragma unroll
    for (int i = 0; i < 4; i++) {
        float inv = 1.0f / lrow[i];
        int qr = qr0 + i;
        #pragma unroll
        for (int j = 0; j < 8; j++) {
            float lo, hi;
            UNPACK2(lo, hi, Oacc2[i][j]);
            Op[qr * DHEAD + (tx + 8 * j)] = (lo + hi) * inv;
        }
    }
}

// ---------------------------------------------------------------------------
extern "C" void kernel_launch(void* const* d_in, const int* in_sizes, int n_in,
                              void* d_out, int out_size)
{
    const float* X  = (const float*)d_in[0];
    const float* Wq = (const float*)d_in[1];
    const float* Wk = (const float*)d_in[2];
    const float* Wv = (const float*)d_in[3];
    const float* Wo = (const float*)d_in[4];
    float* out = (float*)d_out;

    cudaFuncSetAttribute(attn_kernel,
                         cudaFuncAttributeMaxDynamicSharedMemorySize, ATTN_SMEM);
    cudaFuncSetAttribute(mma_gemm_kernel,
                         cudaFuncAttributeMaxDynamicSharedMemorySize, GEMM_SMEM);

    float *xh, *xl, *bh, *bl, *oh, *ol, *wh, *wl;
    cudaGetSymbolAddress((void**)&xh, g_Xh);
    cudaGetSymbolAddress((void**)&xl, g_Xl);
    cudaGetSymbolAddress((void**)&bh, g_Bh);
    cudaGetSymbolAddress((void**)&bl, g_Bl);
    cudaGetSymbolAddress((void**)&oh, g_Oh);
    cudaGetSymbolAddress((void**)&ol, g_Ol);
    cudaGetSymbolAddress((void**)&wh, g_WOh);
    cudaGetSymbolAddress((void**)&wl, g_WOl);

    split_x_kernel<<<8192, 256>>>(X);
    split_wqkv_kernel<<<12288, 256>>>(Wq, Wk, Wv);
    split_wout_kernel<<<4096, 256>>>(Wo);

    mma_gemm_kernel<<<dim3(24, 64), 256, GEMM_SMEM>>>(xh, xl, bh, bl, nullptr, 0);
    attn_kernel<<<dim3(16, BATCH * NHEADS), 256, ATTN_SMEM>>>();
    split_o_kernel<<<8192, 256>>>();
    mma_gemm_kernel<<<dim3(8, 64), 256, GEMM_SMEM>>>(oh, ol, wh, wl, out, 1);
}

// round 16
// speedup vs baseline: 1.3348x; 1.1415x over previous
#include <cuda_runtime.h>
#include <math.h>
#include <cstdint>

#define BATCH   4
#define SEQ     2048
#define DMODEL  1024
#define NHEADS  16
#define DHEAD   64
#define HD      (SEQ * DHEAD)          // per (b,h) plane: 131072

typedef unsigned long long ull;

// Scratch (allocation-free rule: __device__ globals).
__device__ float g_Q[BATCH * NHEADS * SEQ * DHEAD];
__device__ float g_K[BATCH * NHEADS * SEQ * DHEAD];
__device__ float g_V[BATCH * NHEADS * SEQ * DHEAD];
__device__ float g_O[BATCH * NHEADS * SEQ * DHEAD];

// tf32 operand planes, k-interleaved layout (see KPERM)
__device__ float g_Xh[8192 * 1024];
__device__ float g_Xl[8192 * 1024];
__device__ float g_Bh[3072 * 1024];    // [n][k] qkv weights^T, tf32-rounded
__device__ float g_Oh[8192 * 1024];    // concat(O) rows, hi
__device__ float g_Ol[8192 * 1024];    //                 lo
__device__ float g_WOh[1024 * 1024];   // Wout^T [n][k], tf32-rounded

// k-interleave: fragment pair (k, k+4) lands contiguous -> float2 LDS
#define KPERM(k) (((k) & ~7) | (((k) & 3) << 1) | (((k) >> 2) & 1))

// ---- helpers --------------------------------------------------------------
#define FMA2(d, a, b) \
    asm("fma.rn.f32x2 %0, %1, %2, %0;" : "+l"(d) : "l"(a), "l"(b))
#define MUL2(d, a, b) \
    asm("mul.rn.f32x2 %0, %1, %2;" : "=l"(d) : "l"(a), "l"(b))
#define PACK2(r, lo, hi) \
    asm("mov.b64 %0, {%1, %2};" : "=l"(r) : "f"(lo), "f"(hi))
#define UNPACK2(lo, hi, r) \
    asm("mov.b64 {%0, %1}, %2;" : "=f"(lo), "=f"(hi) : "l"(r))

__device__ __forceinline__ float ex2f(float x) {
    float y;
    asm("ex2.approx.f32 %0, %1;" : "=f"(y) : "f"(x));
    return y;
}

__device__ __forceinline__ void cp16(void* dst, const void* src) {
    uint32_t d;
    asm("{ .reg .u64 t; cvta.to.shared.u64 t, %1; cvt.u32.u64 %0, t; }"
        : "=r"(d) : "l"(dst));
    asm volatile("cp.async.cg.shared.global [%0], [%1], 16;"
                 :: "r"(d), "l"(src) : "memory");
}
#define CP_COMMIT()  asm volatile("cp.async.commit_group;" ::: "memory")
#define CP_WAIT1()   asm volatile("cp.async.wait_group 1;" ::: "memory")
#define CP_WAIT0()   asm volatile("cp.async.wait_group 0;" ::: "memory")

__device__ __forceinline__ float tf32r(float x) {
    uint32_t b;
    asm("cvt.rna.tf32.f32 %0, %1;" : "=r"(b) : "f"(x));
    return __uint_as_float(b);
}
__device__ __forceinline__ void tf32_split(float x, float& h, float& l) {
    h = tf32r(x);
    l = tf32r(x - h);
}

// m16n8k8 TF32 MMA, fp32 accumulate (sm_80+ PTX, legal at compute_103)
#define MMA_TF32(c, a0, a1, a2, a3, b0, b1)                                  \
    asm volatile("mma.sync.aligned.m16n8k8.row.col.f32.tf32.tf32.f32 "       \
        "{%0,%1,%2,%3}, {%4,%5,%6,%7}, {%8,%9}, {%0,%1,%2,%3};"              \
        : "+f"((c)[0]), "+f"((c)[1]), "+f"((c)[2]), "+f"((c)[3])             \
        : "r"(a0), "r"(a1), "r"(a2), "r"(a3), "r"(b0), "r"(b1))

// ---------------------------------------------------------------------------
// Prep kernels: tf32 splits/rounds into k-interleaved planes
// ---------------------------------------------------------------------------
__global__ __launch_bounds__(256) void split_x_kernel(const float* __restrict__ X) {
    int i4 = blockIdx.x * 256 + threadIdx.x;       // over 8192*1024/4
    int idx = i4 * 4;
    int r = idx >> 10, k0 = idx & 1023;
    float4 v = *(const float4*)&X[(size_t)idx];
    float h, l;
    #pragma unroll
    for (int j = 0; j < 4; j++) {
        float x = (j == 0) ? v.x : (j == 1) ? v.y : (j == 2) ? v.z : v.w;
        tf32_split(x, h, l);
        int p = r * 1024 + KPERM(k0 + j);
        g_Xh[p] = h; g_Xl[p] = l;
    }
}

// g_Bh[n][k], n = which*1024 + h*64 + d; source W[h][k][d]; hi-only
__global__ __launch_bounds__(256) void round_wqkv_kernel(
    const float* __restrict__ Wq, const float* __restrict__ Wk,
    const float* __restrict__ Wv) {
    int idx = blockIdx.x * 256 + threadIdx.x;      // over 3072*1024
    int n = idx >> 10, k = idx & 1023;
    int which = n >> 10, h = (n & 1023) >> 6, d = n & 63;
    const float* W = (which == 0) ? Wq : (which == 1) ? Wk : Wv;
    g_Bh[n * 1024 + KPERM(k)] = tf32r(W[h * (DMODEL * DHEAD) + k * DHEAD + d]);
}

__global__ __launch_bounds__(256) void round_wout_kernel(const float* __restrict__ Wo) {
    int idx = blockIdx.x * 256 + threadIdx.x;      // over 1024*1024
    int n = idx >> 10, k = idx & 1023;
    g_WOh[n * 1024 + KPERM(k)] = tf32r(Wo[k * 1024 + n]);
}

// g_O [b,h,s,d] -> concat rows [r][m], split hi/lo, k-interleaved
__global__ __launch_bounds__(256) void split_o_kernel() {
    int i4 = blockIdx.x * 256 + threadIdx.x;       // over 8192*1024/4
    int idx = i4 * 4;
    int r = idx >> 10, m = idx & 1023;
    int h = m >> 6, d = m & 63;
    int b = r >> 11, s = r & 2047;
    float4 v = *(const float4*)&g_O[((b * NHEADS + h) * SEQ + s) * DHEAD + d];
    float hh, ll;
    #pragma unroll
    for (int j = 0; j < 4; j++) {
        float x = (j == 0) ? v.x : (j == 1) ? v.y : (j == 2) ? v.z : v.w;
        tf32_split(x, hh, ll);
        int p = r * 1024 + KPERM(m + j);
        g_Oh[p] = hh; g_Ol[p] = ll;
    }
}

// ---------------------------------------------------------------------------
// TF32 MMA GEMM, 2-term split: C = Ah*B + Al*B (B tf32-rounded).
// 128x128 CTA tile, 8 warps 2x4 (warp 64x32), k-tile 32, cp.async 2-stage.
// Operand planes are k-interleaved -> all fragment loads are float2.
// mode 0: scatter to g_Q/K/V; mode 1: row-major out.
// ---------------------------------------------------------------------------
#define GK    32
#define GSTR  36                               // 144 B rows, 16B-aligned
#define GEMM_SMEM (4 * 128 * GSTR * 4)         // A[2]+B[2] = 73728 B

__global__ __launch_bounds__(256) void mma_gemm_kernel(
    const float* __restrict__ A0, const float* __restrict__ A1,
    const float* __restrict__ B0,
    float* __restrict__ outp, int mode)
{
    extern __shared__ float sm[];
    float* smA = sm;                           // [2][128][GSTR]
    float* smB = sm + 2 * 128 * GSTR;          // [2][128][GSTR]

    const int t    = threadIdx.x;
    const int w    = t >> 5, lane = t & 31;
    const int gid  = lane >> 2, tin = lane & 3;
    const int wm   = w >> 2, wn = w & 3;       // 2 x 4 warp grid
    const int rowBase = blockIdx.y * 128;
    const int colBase = blockIdx.x * 128;

    float acc[4][4][4];
    #pragma unroll
    for (int mt = 0; mt < 4; mt++)
        #pragma unroll
        for (int nt = 0; nt < 4; nt++)
            #pragma unroll
            for (int i = 0; i < 4; i++) acc[mt][nt][i] = 0.0f;

    const int nIt = 64;                        // 2 segments x 32 k-tiles

    auto issue = [&](int it, int st) {
        const int seg = it >> 5, k0 = (it & 31) * GK;
        const float* Asrc = seg ? A1 : A0;
        #pragma unroll
        for (int i = 0; i < 4; i++) {          // A: 1024 16B chunks
            int idx = t + i * 256;
            int r = idx >> 3, c4 = (idx & 7) * 4;
            cp16(&smA[(st * 128 + r) * GSTR + c4],
                 &Asrc[(size_t)(rowBase + r) * 1024 + k0 + c4]);
        }
        #pragma unroll
        for (int i = 0; i < 4; i++) {          // B: 1024 16B chunks
            int idx = t + i * 256;
            int r = idx >> 3, c4 = (idx & 7) * 4;
            cp16(&smB[(st * 128 + r) * GSTR + c4],
                 &B0[(size_t)(colBase + r) * 1024 + k0 + c4]);
        }
        CP_COMMIT();
    };

    issue(0, 0);
    for (int it = 0; it < nIt; it++) {
        const int st = it & 1;
        if (it + 1 < nIt) { issue(it + 1, st ^ 1); CP_WAIT1(); }
        else              { CP_WAIT0(); }
        __syncthreads();

        const float* As = smA + st * 128 * GSTR;
        const float* Bs = smB + st * 128 * GSTR;

        #pragma unroll
        for (int ks = 0; ks < 4; ks++) {
            const int kp = ks * 8 + tin * 2;   // interleaved pair (k, k+4)
            float2 bfr[4];
            #pragma unroll
            for (int nt = 0; nt < 4; nt++) {
                int n = wn * 32 + nt * 8 + gid;
                bfr[nt] = *(const float2*)&Bs[n * GSTR + kp];
            }
            #pragma unroll
            for (int mt = 0; mt < 4; mt++) {
                int r0 = wm * 64 + mt * 16 + gid, r1 = r0 + 8;
                float2 alo = *(const float2*)&As[r0 * GSTR + kp];
                float2 ahi = *(const float2*)&As[r1 * GSTR + kp];
                uint32_t a0 = __float_as_uint(alo.x);
                uint32_t a1 = __float_as_uint(ahi.x);
                uint32_t a2 = __float_as_uint(alo.y);
                uint32_t a3 = __float_as_uint(ahi.y);
                #pragma unroll
                for (int nt = 0; nt < 4; nt++)
                    MMA_TF32(acc[mt][nt], a0, a1, a2, a3,
                             __float_as_uint(bfr[nt].x), __float_as_uint(bfr[nt].y));
            }
        }
        __syncthreads();
    }

    if (mode == 0) {
        #pragma unroll
        for (int mt = 0; mt < 4; mt++) {
            int r0 = rowBase + wm * 64 + mt * 16 + gid, r1 = r0 + 8;
            int b0i = r0 >> 11, s0 = r0 & 2047;
            int b1i = r1 >> 11, s1 = r1 & 2047;
            #pragma unroll
            for (int nt = 0; nt < 4; nt++) {
                int col = colBase + wn * 32 + nt * 8 + 2 * tin;
                int which = col >> 10;
                float* dst = (which == 0) ? g_Q : (which == 1) ? g_K : g_V;
                int h = (col & 1023) >> 6, d = col & 63;
                *(float2*)&dst[((b0i * NHEADS + h) * SEQ + s0) * DHEAD + d] =
                    make_float2(acc[mt][nt][0], acc[mt][nt][1]);
                *(float2*)&dst[((b1i * NHEADS + h) * SEQ + s1) * DHEAD + d] =
                    make_float2(acc[mt][nt][2], acc[mt][nt][3]);
            }
        }
    } else {
        #pragma unroll
        for (int mt = 0; mt < 4; mt++) {
            int r0 = rowBase + wm * 64 + mt * 16 + gid, r1 = r0 + 8;
            #pragma unroll
            for (int nt = 0; nt < 4; nt++) {
                int col = colBase + wn * 32 + nt * 8 + 2 * tin;
                *(float2*)&outp[(size_t)r0 * 1024 + col] =
                    make_float2(acc[mt][nt][0], acc[mt][nt][1]);
                *(float2*)&outp[(size_t)r1 * 1024 + col] =
                    make_float2(acc[mt][nt][2], acc[mt][nt][3]);
            }
        }
    }
}

// ---------------------------------------------------------------------------
// Kernel 2: causal flash attention (unchanged from passing R15 kernel)
// ---------------------------------------------------------------------------
#define STR 66
#define ATTN_SMEM ((128 * STR + 64 * STR + 64 * STR + 128 * STR) * 4)  // 101376 B

__global__ __launch_bounds__(256) void attn_kernel()
{
    extern __shared__ float smf[];
    float* Qs  = smf;
    float* Ks  = Qs + 128 * STR;
    float* VsT = Ks + 64 * STR;
    float* Ps  = VsT + 64 * STR;

    const int t  = threadIdx.x;
    const int tx = t & 7;
    const int ty = t >> 3;
    const int qt = (gridDim.x - 1) - blockIdx.x;
    const int bh = blockIdx.y;

    const float* __restrict__ Qp = g_Q + bh * HD;
    const float* __restrict__ Kp = g_K + bh * HD;
    const float* __restrict__ Vp = g_V + bh * HD;

    const float SCALE = 0.125f * 1.4426950408889634f;

    #pragma unroll
    for (int i = 0; i < 8; i++) {
        int idx = t + i * 256;
        int r = idx >> 4, d4 = (idx & 15) * 4;
        float4 v = *(const float4*)&Qp[(qt * 128 + r) * DHEAD + d4];
        Qs[r * STR + d4 + 0] = v.x;  Qs[r * STR + d4 + 1] = v.y;
        Qs[r * STR + d4 + 2] = v.z;  Qs[r * STR + d4 + 3] = v.w;
    }

    float mrow[4], lrow[4];
    ull Oacc2[4][8];
    #pragma unroll
    for (int i = 0; i < 4; i++) {
        mrow[i] = -INFINITY;
        lrow[i] = 0.0f;
        #pragma unroll
        for (int j = 0; j < 8; j++) Oacc2[i][j] = 0ull;
    }

    const int nkt = 2 * qt + 2;
    const int qr0 = qt * 128 + ty * 4;

    float4 kreg[4], vreg[4];
    auto ldKV = [&](int jt) {
        #pragma unroll
        for (int i = 0; i < 4; i++) {
            int idx = t + i * 256;
            int c = idx >> 4, d4 = (idx & 15) * 4;
            kreg[i] = *(const float4*)&Kp[(jt * 64 + c) * DHEAD + d4];
            vreg[i] = *(const float4*)&Vp[(jt * 64 + c) * DHEAD + d4];
        }
    };
    ldKV(0);

    for (int jt = 0; jt < nkt; jt++) {
        #pragma unroll
        for (int i = 0; i < 4; i++) {
            int idx = t + i * 256;
            int c = idx >> 4, d4 = (idx & 15) * 4;
            Ks[c * STR + d4 + 0] = kreg[i].x;  Ks[c * STR + d4 + 1] = kreg[i].y;
            Ks[c * STR + d4 + 2] = kreg[i].z;  Ks[c * STR + d4 + 3] = kreg[i].w;
            VsT[(d4 + 0) * STR + c] = vreg[i].x;  VsT[(d4 + 1) * STR + c] = vreg[i].y;
            VsT[(d4 + 2) * STR + c] = vreg[i].z;  VsT[(d4 + 3) * STR + c] = vreg[i].w;
        }
        __syncthreads();

        if (jt + 1 < nkt) ldKV(jt + 1);

        ull sc2[4][8];
        #pragma unroll
        for (int i = 0; i < 4; i++)
            #pragma unroll
            for (int j = 0; j < 8; j++) sc2[i][j] = 0ull;

        #pragma unroll 8
        for (int dp = 0; dp < 32; dp++) {
            ull q2[4], k2[8];
            #pragma unroll
            for (int i = 0; i < 4; i++)
                q2[i] = *(const ull*)&Qs[(ty * 4 + i) * STR + 2 * dp];
            #pragma unroll
            for (int j = 0; j < 8; j++)
                k2[j] = *(const ull*)&Ks[(tx + 8 * j) * STR + 2 * dp];
            #pragma unroll
            for (int i = 0; i < 4; i++)
                #pragma unroll
                for (int j = 0; j < 8; j++)
                    FMA2(sc2[i][j], q2[i], k2[j]);
        }

        #pragma unroll
        for (int i = 0; i < 4; i++) {
            const int qr = qr0 + i;
            float s[8];
            float pm = -INFINITY;
            #pragma unroll
            for (int j = 0; j < 8; j++) {
                float lo, hi;
                UNPACK2(lo, hi, sc2[i][j]);
                float v = (lo + hi) * SCALE;
                int kc = jt * 64 + tx + 8 * j;
                v = (kc <= qr) ? v : -INFINITY;
                s[j] = v;
                pm = fmaxf(pm, v);
            }
            pm = fmaxf(pm, __shfl_xor_sync(0xffffffffu, pm, 1));
            pm = fmaxf(pm, __shfl_xor_sync(0xffffffffu, pm, 2));
            pm = fmaxf(pm, __shfl_xor_sync(0xffffffffu, pm, 4));

            float newm = fmaxf(mrow[i], pm);
            float corr = ex2f(mrow[i] - newm);
            mrow[i] = newm;

            float psum = 0.0f;
            #pragma unroll
            for (int j = 0; j < 8; j++) {
                float p = ex2f(s[j] - newm);
                s[j] = p;
                psum += p;
            }
            psum += __shfl_xor_sync(0xffffffffu, psum, 1);
            psum += __shfl_xor_sync(0xffffffffu, psum, 2);
            psum += __shfl_xor_sync(0xffffffffu, psum, 4);

            lrow[i] = lrow[i] * corr + psum;
            ull corr2;
            PACK2(corr2, corr, corr);
            #pragma unroll
            for (int j = 0; j < 8; j++) MUL2(Oacc2[i][j], Oacc2[i][j], corr2);

            #pragma unroll
            for (int j = 0; j < 8; j++)
                Ps[(ty * 4 + i) * STR + (tx + 8 * j)] = s[j];
        }
        __syncthreads();

        #pragma unroll 8
        for (int cp = 0; cp < 32; cp++) {
            ull p2[4], v2[8];
            #pragma unroll
            for (int i = 0; i < 4; i++)
                p2[i] = *(const ull*)&Ps[(ty * 4 + i) * STR + 2 * cp];
            #pragma unroll
            for (int j = 0; j < 8; j++)
                v2[j] = *(const ull*)&VsT[(tx + 8 * j) * STR + 2 * cp];
            #pragma unroll
            for (int i = 0; i < 4; i++)
                #pragma unroll
                for (int j = 0; j < 8; j++)
                    FMA2(Oacc2[i][j], p2[i], v2[j]);
        }
        __syncthreads();
    }

    float* __restrict__ Op = g_O + bh * HD;
    #pragma unroll
    for (int i = 0; i < 4; i++) {
        float inv = 1.0f / lrow[i];
        int qr = qr0 + i;
        #pragma unroll
        for (int j = 0; j < 8; j++) {
            float lo, hi;
            UNPACK2(lo, hi, Oacc2[i][j]);
            Op[qr * DHEAD + (tx + 8 * j)] = (lo + hi) * inv;
        }
    }
}

// ---------------------------------------------------------------------------
extern "C" void kernel_launch(void* const* d_in, const int* in_sizes, int n_in,
                              void* d_out, int out_size)
{
    const float* X  = (const float*)d_in[0];
    const float* Wq = (const float*)d_in[1];
    const float* Wk = (const float*)d_in[2];
    const float* Wv = (const float*)d_in[3];
    const float* Wo = (const float*)d_in[4];
    float* out = (float*)d_out;

    cudaFuncSetAttribute(attn_kernel,
                         cudaFuncAttributeMaxDynamicSharedMemorySize, ATTN_SMEM);
    cudaFuncSetAttribute(mma_gemm_kernel,
                         cudaFuncAttributeMaxDynamicSharedMemorySize, GEMM_SMEM);

    float *xh, *xl, *bh, *oh, *ol, *wh;
    cudaGetSymbolAddress((void**)&xh, g_Xh);
    cudaGetSymbolAddress((void**)&xl, g_Xl);
    cudaGetSymbolAddress((void**)&bh, g_Bh);
    cudaGetSymbolAddress((void**)&oh, g_Oh);
    cudaGetSymbolAddress((void**)&ol, g_Ol);
    cudaGetSymbolAddress((void**)&wh, g_WOh);

    split_x_kernel<<<8192, 256>>>(X);
    round_wqkv_kernel<<<12288, 256>>>(Wq, Wk, Wv);
    round_wout_kernel<<<4096, 256>>>(Wo);

    mma_gemm_kernel<<<dim3(24, 64), 256, GEMM_SMEM>>>(xh, xl, bh, nullptr, 0);
    attn_kernel<<<dim3(16, BATCH * NHEADS), 256, ATTN_SMEM>>>();
    split_o_kernel<<<8192, 256>>>();
    mma_gemm_kernel<<<dim3(8, 64), 256, GEMM_SMEM>>>(oh, ol, wh, out, 1);
}